// round 12
// baseline (speedup 1.0000x reference)
#include <cuda_runtime.h>
#include <math.h>

#define NN 4096
#define DD 256
#define SS 32
#define KK 4
#define NDOUT (NN*DD)
#define NNZ_MAX (1<<20)
#define FULLM 0xffffffffu
#define MCH 32            // Mpart chunks per k (each chunk = NN/MCH = 128 rows)

// ---------------- scratch (device globals; no allocation allowed) -----------
__device__ int   g_rowbeg[NN];
__device__ int   g_rowcnt[NN];
__device__ int   g_diagpos[NN];
__device__ int   g_nnz = 0;          // reset to 0 at end of every call (k_lap2)
__device__ int   g_mcnt[KK];         // last-block counters; reset by last block
__device__ unsigned short g_cols[NNZ_MAX];
__device__ __align__(16) float g_Z  [KK*NN*SS];
__device__ __align__(16) float g_V  [KK*NN*SS];
__device__ __align__(16) float g_W  [KK*NN*SS];
__device__ __align__(16) float g_Mp  [KK*MCH*SS*SS];
__device__ float g_Minv[KK*SS*SS];
__device__ float g_w[KK];

// ------- CSR build (pattern only; L implicit since A is 0/1) + orth + init ---
// blocks [0,NN): build row; blocks [NN,NN+10): orth_loss pairs.
__global__ void k_build(const float* __restrict__ A, const float* __restrict__ U,
                        const float* __restrict__ hw, float* out, int out_size) {
    __shared__ int slist[16 * 256];
    __shared__ int s_wsum[8], s_woff[8];
    __shared__ int s_base, s_total;
    // ---- orth blocks ----
    if (blockIdx.x >= NN) {
        const int pk[10] = {0,1,2,3, 0,0,0, 1,1, 2};
        const int pl[10] = {0,1,2,3, 1,2,3, 2,3, 3};
        int q = blockIdx.x - NN;
        int k = pk[q], l = pl[q];
        __shared__ float sa[32][33];
        __shared__ float sb[32][33];
        __shared__ float sred[256];
        const float* Ua = U + (size_t)k * DD * SS;
        const float* Ub = U + (size_t)l * DD * SS;
        int t = threadIdx.x;
        int b = t & 31, a0 = (t >> 5) * 4;
        float acc[4] = {0.f, 0.f, 0.f, 0.f};
        for (int d0 = 0; d0 < DD; d0 += 32) {
            for (int i = t; i < 1024; i += 256) {
                sa[i >> 5][i & 31] = Ua[(size_t)(d0 + (i >> 5)) * SS + (i & 31)];
                sb[i >> 5][i & 31] = Ub[(size_t)(d0 + (i >> 5)) * SS + (i & 31)];
            }
            __syncthreads();
            #pragma unroll 8
            for (int dd = 0; dd < 32; dd++) {
                float vb = sb[dd][b];
                #pragma unroll
                for (int i = 0; i < 4; i++) acc[i] += sa[dd][a0 + i] * vb;
            }
            __syncthreads();
        }
        float local = 0.f;
        #pragma unroll
        for (int i = 0; i < 4; i++) {
            float g = acc[i];
            if (k == l && (a0 + i) == b) g -= 1.f;
            local += g * g;
        }
        sred[t] = local;
        __syncthreads();
        for (int o = 128; o > 0; o >>= 1) {
            if (t < o) sred[t] += sred[t + o];
            __syncthreads();
        }
        if (t == 0) atomicAdd(&out[NDOUT], sred[0]);
        return;
    }
    // ---- build blocks ----
    int row = blockIdx.x, t = threadIdx.x;
    int lane = t & 31, wid = t >> 5;
    if (row == 0 && t == 0) {
        float m = hw[0];
        for (int i = 1; i < KK; i++) m = fmaxf(m, hw[i]);
        float e[KK]; float s = 0.f;
        for (int i = 0; i < KK; i++) { e[i] = expf(hw[i] - m); s += e[i]; }
        for (int i = 0; i < KK; i++) {
            float w = e[i] / s;
            g_w[i] = w;
            if (NDOUT + 2 + i < out_size) out[NDOUT + 2 + i] = w;
        }
        if (NDOUT     < out_size) out[NDOUT]     = 0.f;
        if (NDOUT + 1 < out_size) out[NDOUT + 1] = 0.f;
    }
    const float4* ar = (const float4*)(A + (size_t)row * NN);
    float4 ff[4];
    ff[0] = ar[t * 4 + 0];
    ff[1] = ar[t * 4 + 1];
    ff[2] = ar[t * 4 + 2];
    ff[3] = ar[t * 4 + 3];
    int c = 0;
    int cb = t * 16;
    #pragma unroll
    for (int i = 0; i < 4; i++) {
        if (ff[i].x != 0.f) slist[(c++) * 256 + t] = cb + i * 4;
        if (ff[i].y != 0.f) slist[(c++) * 256 + t] = cb + i * 4 + 1;
        if (ff[i].z != 0.f) slist[(c++) * 256 + t] = cb + i * 4 + 2;
        if (ff[i].w != 0.f) slist[(c++) * 256 + t] = cb + i * 4 + 3;
    }
    // warp-shuffle inclusive scan of c
    int inc = c;
    #pragma unroll
    for (int off = 1; off < 32; off <<= 1) {
        int v = __shfl_up_sync(FULLM, inc, off);
        if (lane >= off) inc += v;
    }
    if (lane == 31) s_wsum[wid] = inc;
    __syncthreads();
    if (t < 8) {
        int v = s_wsum[t];
        int sc = v;
        #pragma unroll
        for (int off = 1; off < 8; off <<= 1) {
            int u = __shfl_up_sync(0xff, sc, off);
            if (t >= off) sc += u;
        }
        s_woff[t] = sc - v;
        if (t == 7) {
            s_total = sc;
            s_base = atomicAdd(&g_nnz, sc);
            g_rowcnt[row] = sc;
            g_rowbeg[row] = s_base;
        }
    }
    __syncthreads();
    int excl = (inc - c) + s_woff[wid];
    int base = s_base;
    for (int j = 0; j < c; j++) {
        int col = slist[j * 256 + t];
        int pos = base + excl + j;
        if (pos < NNZ_MAX) g_cols[pos] = (unsigned short)col;
        if (col == row) g_diagpos[row] = excl + j;
    }
}

// ---- Z[k] = U[k]^T @ hops[k]^T, 64n x 32s tile, register double-buffered ----
__global__ void __launch_bounds__(256) k_Z(const float* __restrict__ hops,
                                           const float* __restrict__ U) {
    __shared__ float sh[64 * 33];
    __shared__ __align__(16) float sU[DD * SS];   // 32 KB: full U[k]
    int k = blockIdx.y, n0 = blockIdx.x * 64;
    int t = threadIdx.x;
    int sq = t >> 5, nq = t & 31;
    int n = t >> 3, dq = (t & 7) * 4;

    const float4* up = (const float4*)(U + (size_t)k * DD * SS);
    #pragma unroll
    for (int p = 0; p < 8; p++)
        ((float4*)sU)[t + p * 256] = up[t + p * 256];

    const float* hb = hops + ((size_t)k * NN + n0) * DD;
    float4 va = *(const float4*)&hb[(size_t)n * DD + dq];
    float4 vb = *(const float4*)&hb[(size_t)(n + 32) * DD + dq];

    float acc[2][4];
    #pragma unroll
    for (int i = 0; i < 2; i++)
        #pragma unroll
        for (int j = 0; j < 4; j++) acc[i][j] = 0.f;

    #pragma unroll
    for (int c = 0; c < 8; c++) {
        float* p0 = &sh[n * 33 + dq];
        p0[0] = va.x; p0[1] = va.y; p0[2] = va.z; p0[3] = va.w;
        float* p1 = &sh[(n + 32) * 33 + dq];
        p1[0] = vb.x; p1[1] = vb.y; p1[2] = vb.z; p1[3] = vb.w;
        __syncthreads();
        if (c < 7) {
            va = *(const float4*)&hb[(size_t)n * DD + (c + 1) * 32 + dq];
            vb = *(const float4*)&hb[(size_t)(n + 32) * DD + (c + 1) * 32 + dq];
        }
        const float* ub = &sU[c * 32 * 32];
        #pragma unroll
        for (int dd = 0; dd < 32; dd++) {
            float4 u = *(const float4*)&ub[dd * 32 + sq * 4];
            float h0 = sh[(nq     ) * 33 + dd];
            float h1 = sh[(nq + 32) * 33 + dd];
            acc[0][0] += h0 * u.x; acc[0][1] += h0 * u.y; acc[0][2] += h0 * u.z; acc[0][3] += h0 * u.w;
            acc[1][0] += h1 * u.x; acc[1][1] += h1 * u.y; acc[1][2] += h1 * u.z; acc[1][3] += h1 * u.w;
        }
        __syncthreads();
    }
    #pragma unroll
    for (int ni = 0; ni < 2; ni++) {
        float4 o = make_float4(acc[ni][0], acc[ni][1], acc[ni][2], acc[ni][3]);
        *(float4*)&g_Z[((size_t)k * NN + n0 + nq + 32 * ni) * SS + sq * 4] = o;
    }
}

// ---- M partials: Z^T Z over 128-row chunks; LAST block per k also inverts ---
__global__ void __launch_bounds__(256) k_Mpart() {
    __shared__ __align__(16) float sZ[128 * 32];   // 16 KB (reused as sM + GJ area)
    __shared__ bool s_last;
    int k = blockIdx.y, c = blockIdx.x;
    int t = threadIdx.x;
    const float4* Zb = (const float4*)(g_Z + ((size_t)k * NN + c * 128) * SS);
    #pragma unroll
    for (int i = 0; i < 4; i++)
        ((float4*)sZ)[t + i * 256] = Zb[t + i * 256];
    __syncthreads();
    int a = t >> 3, b4 = (t & 7) * 4;
    float acc[4] = {0.f, 0.f, 0.f, 0.f};
    #pragma unroll 4
    for (int r = 0; r < 128; r++) {
        float za = sZ[r * 32 + a];
        float4 zb = *(const float4*)&sZ[r * 32 + b4];
        acc[0] += za * zb.x; acc[1] += za * zb.y;
        acc[2] += za * zb.z; acc[3] += za * zb.w;
    }
    float4 o = make_float4(acc[0], acc[1], acc[2], acc[3]);
    *(float4*)&g_Mp[((size_t)(k * MCH + c)) * 1024 + a * 32 + b4] = o;

    // last-block reduction + 32x32 SPD inverse
    __threadfence();
    if (t == 0) {
        int v = atomicAdd(&g_mcnt[k], 1);
        s_last = (v == MCH - 1);
    }
    __syncthreads();
    if (!s_last) return;

    float* sM = sZ;                               // [0,1024)
    float (*ga)[64] = (float(*)[64])(sZ + 1024);  // [1024,3072)
    float r0 = 0.f, r1 = 0.f, r2 = 0.f, r3 = 0.f;
    for (int cc = 0; cc < MCH; cc++) {
        const float* mp = &g_Mp[((size_t)(k * MCH + cc)) * 1024];
        r0 += mp[t]; r1 += mp[t + 256]; r2 += mp[t + 512]; r3 += mp[t + 768];
    }
    __syncthreads();   // all reads of sZ (as Z) done before overwrite
    const float coeff = (float)SS / ((float)NN * 0.25f);
    int i0 = t, i1 = t + 256, i2 = t + 512, i3 = t + 768;
    sM[i0] = coeff * r0 + (((i0 >> 5) == (i0 & 31)) ? 1.f : 0.f);
    sM[i1] = coeff * r1 + (((i1 >> 5) == (i1 & 31)) ? 1.f : 0.f);
    sM[i2] = coeff * r2 + (((i2 >> 5) == (i2 & 31)) ? 1.f : 0.f);
    sM[i3] = coeff * r3 + (((i3 >> 5) == (i3 & 31)) ? 1.f : 0.f);
    __syncthreads();
    if (t < 32) {
        int j = t;
        for (int r = 0; r < 32; r++) {
            ga[r][j]      = sM[r * 32 + j];
            ga[r][32 + j] = (r == j) ? 1.f : 0.f;
        }
        __syncwarp();
        for (int p = 0; p < 32; p++) {
            float pv = 1.0f / ga[p][p];
            __syncwarp();
            ga[p][j]      *= pv;
            ga[p][32 + j] *= pv;
            __syncwarp();
            for (int r = 0; r < 32; r++) {
                if (r == p) continue;
                float f = ga[r][p];
                __syncwarp();
                ga[r][j]      -= f * ga[p][j];
                ga[r][32 + j] -= f * ga[p][32 + j];
                __syncwarp();
            }
            __syncwarp();
        }
        for (int r = 0; r < 32; r++)
            g_Minv[k * 1024 + r * 32 + j] = ga[r][32 + j];
        if (j == 0) g_mcnt[k] = 0;   // clean for next replay
    }
}

// ---- warp-per-row online softmax on CSR support; M^-1 applied per row -------
// score(i,j) = (M^-1 z_i) . z_j ; V_i = M^-1 (sum_j alpha_ij z_j)
__global__ void __launch_bounds__(256) k_score() {
    __shared__ float sMinv[32 * 33];
    __shared__ float sZr[8][32];
    int k = blockIdx.y;
    int t = threadIdx.x;
    int w = t >> 5, lane = t & 31;
    int g = lane >> 3, sq = lane & 7;
    for (int i = t; i < 1024; i += 256)
        sMinv[(i >> 5) * 33 + (i & 31)] = g_Minv[k * 1024 + i];
    int row = blockIdx.x * 8 + w;
    int beg = g_rowbeg[row];
    int cnt = g_rowcnt[row];
    const float* Zb = g_Z + (size_t)k * NN * SS;
    float4 z4 = *(const float4*)&Zb[(size_t)row * SS + sq * 4];
    if (g == 0) {
        sZr[w][sq * 4 + 0] = z4.x; sZr[w][sq * 4 + 1] = z4.y;
        sZr[w][sq * 4 + 2] = z4.z; sZr[w][sq * 4 + 3] = z4.w;
    }
    __syncthreads();
    // y = M^-1 z (each lane: its 4 s-components)
    float y4[4];
    #pragma unroll
    for (int cc = 0; cc < 4; cc++) {
        int s = sq * 4 + cc;
        float a = 0.f;
        #pragma unroll
        for (int tt = 0; tt < 32; tt++)
            a += sMinv[s * 33 + tt] * sZr[w][tt];
        y4[cc] = a;
    }

    float m = -1e30f, l = 0.f;
    float4 vac = make_float4(0.f, 0.f, 0.f, 0.f);
    for (int base = 0; base < cnt; base += 4) {
        int idx = base + g;
        bool valid = idx < cnt;
        int ii = valid ? idx : cnt - 1;
        int col = (int)__ldg(&g_cols[beg + ii]);
        float4 f4 = *(const float4*)&Zb[(size_t)col * SS + sq * 4];
        float p = y4[0] * f4.x + y4[1] * f4.y + y4[2] * f4.z + y4[3] * f4.w;
        p += __shfl_xor_sync(FULLM, p, 1);
        p += __shfl_xor_sync(FULLM, p, 2);
        p += __shfl_xor_sync(FULLM, p, 4);
        if (valid) {
            float nm = fmaxf(m, p);
            float sc = __expf(m - nm);
            float e  = __expf(p - nm);
            l = l * sc + e;
            vac.x = vac.x * sc + e * f4.x;
            vac.y = vac.y * sc + e * f4.y;
            vac.z = vac.z * sc + e * f4.z;
            vac.w = vac.w * sc + e * f4.w;
            m = nm;
        }
    }
    #pragma unroll
    for (int off = 8; off < 32; off <<= 1) {
        float mo = __shfl_xor_sync(FULLM, m, off);
        float lo = __shfl_xor_sync(FULLM, l, off);
        float vx = __shfl_xor_sync(FULLM, vac.x, off);
        float vy = __shfl_xor_sync(FULLM, vac.y, off);
        float vz = __shfl_xor_sync(FULLM, vac.z, off);
        float vw = __shfl_xor_sync(FULLM, vac.w, off);
        float nm = fmaxf(m, mo);
        float a = __expf(m - nm), b = __expf(mo - nm);
        m = nm;
        l = l * a + lo * b;
        vac.x = vac.x * a + vx * b;
        vac.y = vac.y * a + vy * b;
        vac.z = vac.z * a + vz * b;
        vac.w = vac.w * a + vw * b;
    }
    // r = vac / l; V = M^-1 r
    float inv = 1.0f / l;
    if (g == 0) {
        sZr[w][sq * 4 + 0] = vac.x * inv; sZr[w][sq * 4 + 1] = vac.y * inv;
        sZr[w][sq * 4 + 2] = vac.z * inv; sZr[w][sq * 4 + 3] = vac.w * inv;
    }
    __syncwarp();
    if (g == 0) {
        float o4[4];
        #pragma unroll
        for (int cc = 0; cc < 4; cc++) {
            int s = sq * 4 + cc;
            float a = 0.f;
            #pragma unroll
            for (int tt = 0; tt < 32; tt++)
                a += sMinv[s * 33 + tt] * sZr[w][tt];
            o4[cc] = a;
        }
        float4 o = make_float4(o4[0], o4[1], o4[2], o4[3]);
        *(float4*)&g_V[((size_t)k * NN + row) * SS + sq * 4] = o;
    }
}

// ---- warp-per-row: W_k = w_k * (V_k - lam*(cnt*V_row - sum_nbr V_col)) ------
__global__ void __launch_bounds__(256) k_lapV(const float* __restrict__ lamp) {
    int k = blockIdx.y;
    int w = threadIdx.x >> 5, lane = threadIdx.x & 31;
    int g = lane >> 3, sq = lane & 7;
    int row = blockIdx.x * 8 + w;
    float lam = lamp[0];
    int beg = g_rowbeg[row];
    int cnt = g_rowcnt[row];
    const float* Vb = g_V + (size_t)k * NN * SS;
    float4 s4 = make_float4(0.f, 0.f, 0.f, 0.f);
    for (int base = 0; base < cnt; base += 4) {
        int idx = base + g;
        bool valid = idx < cnt;
        int ii = valid ? idx : cnt - 1;
        int col = (int)__ldg(&g_cols[beg + ii]);
        float sgn = valid ? 1.f : 0.f;
        float4 f4 = *(const float4*)&Vb[(size_t)col * SS + sq * 4];
        s4.x += sgn * f4.x; s4.y += sgn * f4.y; s4.z += sgn * f4.z; s4.w += sgn * f4.w;
    }
    #pragma unroll
    for (int off = 8; off < 32; off <<= 1) {
        s4.x += __shfl_xor_sync(FULLM, s4.x, off);
        s4.y += __shfl_xor_sync(FULLM, s4.y, off);
        s4.z += __shfl_xor_sync(FULLM, s4.z, off);
        s4.w += __shfl_xor_sync(FULLM, s4.w, off);
    }
    if (g == 0) {
        float wk = g_w[k];
        float fc = (float)cnt;
        float4 v4 = *(const float4*)&Vb[(size_t)row * SS + sq * 4];
        float4 o = make_float4(wk * (v4.x - lam * (fc * v4.x - s4.x)),
                               wk * (v4.y - lam * (fc * v4.y - s4.y)),
                               wk * (v4.z - lam * (fc * v4.z - s4.z)),
                               wk * (v4.w - lam * (fc * v4.w - s4.w)));
        *(float4*)&g_W[((size_t)k * NN + row) * SS + sq * 4] = o;
    }
}

// ----- H_out = softthresh(hops0 + 0.5 * sum_k W_k @ U_k^T, thr)  (N x D) -----
__global__ void __launch_bounds__(256) k_vu(const float* __restrict__ U,
                                            const float* __restrict__ hops,
                                            const float* __restrict__ thr,
                                            float* __restrict__ out) {
    __shared__ __align__(16) float sW[32 * 32];
    int d = threadIdx.x, n0 = blockIdx.x * 32;
    float acc[32];
    #pragma unroll
    for (int i = 0; i < 32; i++) acc[i] = 0.f;
    for (int k = 0; k < KK; k++) {
        float u[32];
        const float4* up = (const float4*)(U + (size_t)k * DD * SS + (size_t)d * SS);
        #pragma unroll
        for (int i = 0; i < 8; i++) {
            float4 t = __ldg(&up[i]);
            u[4*i]   = t.x; u[4*i+1] = t.y;
            u[4*i+2] = t.z; u[4*i+3] = t.w;
        }
        __syncthreads();
        for (int i = threadIdx.x; i < 1024; i += 256)
            sW[i] = g_W[(size_t)k * NN * SS + (size_t)n0 * SS + i];
        __syncthreads();
        #pragma unroll 4
        for (int n = 0; n < 32; n++) {
            const float4* vp = (const float4*)&sW[n * 32];
            float a = 0.f;
            #pragma unroll
            for (int s4 = 0; s4 < 8; s4++) {
                float4 v = vp[s4];
                a += u[4*s4]*v.x + u[4*s4+1]*v.y + u[4*s4+2]*v.z + u[4*s4+3]*v.w;
            }
            acc[n] += a;
        }
    }
    float t = thr[d];
    for (int n = 0; n < 32; n++) {
        float hh = hops[(size_t)(n0 + n) * DD + d] + 0.5f * acc[n];
        float o = fmaxf(fabsf(hh) - t, 0.f);
        o = (hh < 0.f) ? -o : o;
        out[(size_t)(n0 + n) * DD + d] = o;
    }
}

// ---- lap_smooth = sum((cnt-1)|h_i|^2) - 2 sum_{i<j in N} h_i.h_j ------------
__global__ void k_lap2(float* out) {
    __shared__ int   sc[256];
    __shared__ float sred[256];
    const float* H = out;
    int row = blockIdx.x, d = threadIdx.x;
    int beg = g_rowbeg[row];
    int cnt = g_rowcnt[row];
    int dpos = g_diagpos[row];
    float hi = H[(size_t)row * DD + d];
    float y = 0.f;
    for (int c0 = dpos + 1; c0 < cnt; c0 += 256) {
        int mm = min(256, cnt - c0);
        __syncthreads();
        if (d < mm) sc[d] = (int)g_cols[beg + c0 + d];
        __syncthreads();
        int e = 0;
        for (; e + 4 <= mm; e += 4) {
            float h0 = H[(size_t)sc[e]     * DD + d];
            float h1 = H[(size_t)sc[e + 1] * DD + d];
            float h2 = H[(size_t)sc[e + 2] * DD + d];
            float h3 = H[(size_t)sc[e + 3] * DD + d];
            y += h0 + h1 + h2 + h3;
        }
        for (; e < mm; e++)
            y += H[(size_t)sc[e] * DD + d];
    }
    sred[d] = hi * ((float)(cnt - 1) * hi - 2.f * y);
    __syncthreads();
    for (int o = 128; o > 0; o >>= 1) {
        if (d < o) sred[d] += sred[d + o];
        __syncthreads();
    }
    if (d == 0) {
        atomicAdd(&out[NDOUT + 1], sred[0]);
        if (row == 0) g_nnz = 0;
    }
}

// -----------------------------------------------------------------------------
extern "C" void kernel_launch(void* const* d_in, const int* in_sizes, int n_in,
                              void* d_out, int out_size) {
    const float* hops = (const float*)d_in[0];  // (K,N,D)
    const float* A    = (const float*)d_in[1];  // (N,N)
    const float* U    = (const float*)d_in[3];  // (K,D,S)
    const float* hw   = (const float*)d_in[4];  // (K,)
    const float* thr  = (const float*)d_in[5];  // (D,)
    const float* lam  = (const float*)d_in[6];  // scalar
    float* out = (float*)d_out;

    k_build<<<NN + 10, 256>>>(A, U, hw, out, out_size);

    dim3 gz(NN / 64, KK);
    k_Z<<<gz, 256>>>(hops, U);
    dim3 gm(MCH, KK);
    k_Mpart<<<gm, 256>>>();
    dim3 gmz(NN / 8, KK);
    k_score<<<gmz, 256>>>();
    k_lapV<<<gmz, 256>>>(lam);
    k_vu<<<NN / 32, 256>>>(U, hops, thr, out);
    k_lap2<<<NN, 256>>>(out);
}

// round 15
// speedup vs baseline: 1.0216x; 1.0216x over previous
#include <cuda_runtime.h>
#include <math.h>

#define NN 4096
#define DD 256
#define SS 32
#define KK 4
#define NDOUT (NN*DD)
#define NNZ_MAX (1<<20)
#define FULLM 0xffffffffu
#define MCH 32            // Mpart chunks per k (each chunk = NN/MCH = 128 rows)

// ---------------- scratch (device globals; no allocation allowed) -----------
__device__ int   g_rowbeg[NN];
__device__ int   g_rowcnt[NN];
__device__ int   g_diagpos[NN];
__device__ int   g_nnz = 0;          // reset to 0 at end of every call (k_lap2)
__device__ int   g_mcnt[KK];         // last-block counters; reset by last block
__device__ unsigned short g_cols[NNZ_MAX];
__device__ __align__(16) float g_Z  [KK*NN*SS];
__device__ __align__(16) float g_V  [KK*NN*SS];
__device__ __align__(16) float g_W  [KK*NN*SS];
__device__ __align__(16) float g_Mp  [KK*MCH*SS*SS];
__device__ float g_Minv[KK*SS*SS];
__device__ float g_w[KK];

// ------- CSR build (pattern only; L implicit since A is 0/1) + orth + init ---
__global__ void k_build(const float* __restrict__ A, const float* __restrict__ U,
                        const float* __restrict__ hw, float* out, int out_size) {
    __shared__ int slist[16 * 256];
    __shared__ int s_wsum[8], s_woff[8];
    __shared__ int s_base;
    // ---- orth blocks ----
    if (blockIdx.x >= NN) {
        const int pk[10] = {0,1,2,3, 0,0,0, 1,1, 2};
        const int pl[10] = {0,1,2,3, 1,2,3, 2,3, 3};
        int q = blockIdx.x - NN;
        int k = pk[q], l = pl[q];
        __shared__ float sa[32][33];
        __shared__ float sb[32][33];
        __shared__ float sred[256];
        const float* Ua = U + (size_t)k * DD * SS;
        const float* Ub = U + (size_t)l * DD * SS;
        int t = threadIdx.x;
        int b = t & 31, a0 = (t >> 5) * 4;
        float acc[4] = {0.f, 0.f, 0.f, 0.f};
        for (int d0 = 0; d0 < DD; d0 += 32) {
            for (int i = t; i < 1024; i += 256) {
                sa[i >> 5][i & 31] = Ua[(size_t)(d0 + (i >> 5)) * SS + (i & 31)];
                sb[i >> 5][i & 31] = Ub[(size_t)(d0 + (i >> 5)) * SS + (i & 31)];
            }
            __syncthreads();
            #pragma unroll 8
            for (int dd = 0; dd < 32; dd++) {
                float vb = sb[dd][b];
                #pragma unroll
                for (int i = 0; i < 4; i++) acc[i] += sa[dd][a0 + i] * vb;
            }
            __syncthreads();
        }
        float local = 0.f;
        #pragma unroll
        for (int i = 0; i < 4; i++) {
            float g = acc[i];
            if (k == l && (a0 + i) == b) g -= 1.f;
            local += g * g;
        }
        sred[t] = local;
        __syncthreads();
        for (int o = 128; o > 0; o >>= 1) {
            if (t < o) sred[t] += sred[t + o];
            __syncthreads();
        }
        if (t == 0) atomicAdd(&out[NDOUT], sred[0]);
        return;
    }
    // ---- build blocks ----
    int row = blockIdx.x, t = threadIdx.x;
    int lane = t & 31, wid = t >> 5;
    if (row == 0 && t == 0) {
        float m = hw[0];
        for (int i = 1; i < KK; i++) m = fmaxf(m, hw[i]);
        float e[KK]; float s = 0.f;
        for (int i = 0; i < KK; i++) { e[i] = expf(hw[i] - m); s += e[i]; }
        for (int i = 0; i < KK; i++) {
            float w = e[i] / s;
            g_w[i] = w;
            if (NDOUT + 2 + i < out_size) out[NDOUT + 2 + i] = w;
        }
        if (NDOUT     < out_size) out[NDOUT]     = 0.f;
        if (NDOUT + 1 < out_size) out[NDOUT + 1] = 0.f;
    }
    const float4* ar = (const float4*)(A + (size_t)row * NN);
    float4 ff[4];
    ff[0] = ar[t * 4 + 0];
    ff[1] = ar[t * 4 + 1];
    ff[2] = ar[t * 4 + 2];
    ff[3] = ar[t * 4 + 3];
    int c = 0;
    int cb = t * 16;
    #pragma unroll
    for (int i = 0; i < 4; i++) {
        if (ff[i].x != 0.f) slist[(c++) * 256 + t] = cb + i * 4;
        if (ff[i].y != 0.f) slist[(c++) * 256 + t] = cb + i * 4 + 1;
        if (ff[i].z != 0.f) slist[(c++) * 256 + t] = cb + i * 4 + 2;
        if (ff[i].w != 0.f) slist[(c++) * 256 + t] = cb + i * 4 + 3;
    }
    int inc = c;
    #pragma unroll
    for (int off = 1; off < 32; off <<= 1) {
        int v = __shfl_up_sync(FULLM, inc, off);
        if (lane >= off) inc += v;
    }
    if (lane == 31) s_wsum[wid] = inc;
    __syncthreads();
    if (t < 8) {
        int v = s_wsum[t];
        int sc = v;
        #pragma unroll
        for (int off = 1; off < 8; off <<= 1) {
            int u = __shfl_up_sync(0xff, sc, off);
            if (t >= off) sc += u;
        }
        s_woff[t] = sc - v;
        if (t == 7) {
            s_base = atomicAdd(&g_nnz, sc);
            g_rowcnt[row] = sc;
            g_rowbeg[row] = s_base;
        }
    }
    __syncthreads();
    int excl = (inc - c) + s_woff[wid];
    int base = s_base;
    for (int j = 0; j < c; j++) {
        int col = slist[j * 256 + t];
        int pos = base + excl + j;
        if (pos < NNZ_MAX) g_cols[pos] = (unsigned short)col;
        if (col == row) g_diagpos[row] = excl + j;
    }
}

// ---- Z[k] = U[k]^T @ hops[k]^T, 64n x 32s tile, register double-buffered ----
__global__ void __launch_bounds__(256) k_Z(const float* __restrict__ hops,
                                           const float* __restrict__ U) {
    __shared__ float sh[64 * 33];
    __shared__ __align__(16) float sU[DD * SS];   // 32 KB: full U[k]
    int k = blockIdx.y, n0 = blockIdx.x * 64;
    int t = threadIdx.x;
    int sq = t >> 5, nq = t & 31;
    int n = t >> 3, dq = (t & 7) * 4;

    const float4* up = (const float4*)(U + (size_t)k * DD * SS);
    #pragma unroll
    for (int p = 0; p < 8; p++)
        ((float4*)sU)[t + p * 256] = up[t + p * 256];

    const float* hb = hops + ((size_t)k * NN + n0) * DD;
    float4 va = *(const float4*)&hb[(size_t)n * DD + dq];
    float4 vb = *(const float4*)&hb[(size_t)(n + 32) * DD + dq];

    float acc[2][4];
    #pragma unroll
    for (int i = 0; i < 2; i++)
        #pragma unroll
        for (int j = 0; j < 4; j++) acc[i][j] = 0.f;

    #pragma unroll
    for (int c = 0; c < 8; c++) {
        float* p0 = &sh[n * 33 + dq];
        p0[0] = va.x; p0[1] = va.y; p0[2] = va.z; p0[3] = va.w;
        float* p1 = &sh[(n + 32) * 33 + dq];
        p1[0] = vb.x; p1[1] = vb.y; p1[2] = vb.z; p1[3] = vb.w;
        __syncthreads();
        if (c < 7) {
            va = *(const float4*)&hb[(size_t)n * DD + (c + 1) * 32 + dq];
            vb = *(const float4*)&hb[(size_t)(n + 32) * DD + (c + 1) * 32 + dq];
        }
        const float* ub = &sU[c * 32 * 32];
        #pragma unroll
        for (int dd = 0; dd < 32; dd++) {
            float4 u = *(const float4*)&ub[dd * 32 + sq * 4];
            float h0 = sh[(nq     ) * 33 + dd];
            float h1 = sh[(nq + 32) * 33 + dd];
            acc[0][0] += h0 * u.x; acc[0][1] += h0 * u.y; acc[0][2] += h0 * u.z; acc[0][3] += h0 * u.w;
            acc[1][0] += h1 * u.x; acc[1][1] += h1 * u.y; acc[1][2] += h1 * u.z; acc[1][3] += h1 * u.w;
        }
        __syncthreads();
    }
    #pragma unroll
    for (int ni = 0; ni < 2; ni++) {
        float4 o = make_float4(acc[ni][0], acc[ni][1], acc[ni][2], acc[ni][3]);
        *(float4*)&g_Z[((size_t)k * NN + n0 + nq + 32 * ni) * SS + sq * 4] = o;
    }
}

// ---- M partials: Z^T Z over 128-row chunks; LAST block per k also inverts ---
__global__ void __launch_bounds__(256) k_Mpart() {
    __shared__ __align__(16) float sZ[128 * 32];   // 16 KB (reused as sM + GJ area)
    __shared__ bool s_last;
    int k = blockIdx.y, c = blockIdx.x;
    int t = threadIdx.x;
    const float4* Zb = (const float4*)(g_Z + ((size_t)k * NN + c * 128) * SS);
    #pragma unroll
    for (int i = 0; i < 4; i++)
        ((float4*)sZ)[t + i * 256] = Zb[t + i * 256];
    __syncthreads();
    int a = t >> 3, b4 = (t & 7) * 4;
    float acc[4] = {0.f, 0.f, 0.f, 0.f};
    #pragma unroll 4
    for (int r = 0; r < 128; r++) {
        float za = sZ[r * 32 + a];
        float4 zb = *(const float4*)&sZ[r * 32 + b4];
        acc[0] += za * zb.x; acc[1] += za * zb.y;
        acc[2] += za * zb.z; acc[3] += za * zb.w;
    }
    float4 o = make_float4(acc[0], acc[1], acc[2], acc[3]);
    *(float4*)&g_Mp[((size_t)(k * MCH + c)) * 1024 + a * 32 + b4] = o;

    __threadfence();
    if (t == 0) {
        int v = atomicAdd(&g_mcnt[k], 1);
        s_last = (v == MCH - 1);
    }
    __syncthreads();
    if (!s_last) return;

    float* sM = sZ;
    float (*ga)[64] = (float(*)[64])(sZ + 1024);
    float r0 = 0.f, r1 = 0.f, r2 = 0.f, r3 = 0.f;
    for (int cc = 0; cc < MCH; cc++) {
        const float* mp = &g_Mp[((size_t)(k * MCH + cc)) * 1024];
        r0 += mp[t]; r1 += mp[t + 256]; r2 += mp[t + 512]; r3 += mp[t + 768];
    }
    __syncthreads();
    const float coeff = (float)SS / ((float)NN * 0.25f);
    int i0 = t, i1 = t + 256, i2 = t + 512, i3 = t + 768;
    sM[i0] = coeff * r0 + (((i0 >> 5) == (i0 & 31)) ? 1.f : 0.f);
    sM[i1] = coeff * r1 + (((i1 >> 5) == (i1 & 31)) ? 1.f : 0.f);
    sM[i2] = coeff * r2 + (((i2 >> 5) == (i2 & 31)) ? 1.f : 0.f);
    sM[i3] = coeff * r3 + (((i3 >> 5) == (i3 & 31)) ? 1.f : 0.f);
    __syncthreads();
    if (t < 32) {
        int j = t;
        for (int r = 0; r < 32; r++) {
            ga[r][j]      = sM[r * 32 + j];
            ga[r][32 + j] = (r == j) ? 1.f : 0.f;
        }
        __syncwarp();
        for (int p = 0; p < 32; p++) {
            float pv = 1.0f / ga[p][p];
            __syncwarp();
            ga[p][j]      *= pv;
            ga[p][32 + j] *= pv;
            __syncwarp();
            for (int r = 0; r < 32; r++) {
                if (r == p) continue;
                float f = ga[r][p];
                __syncwarp();
                ga[r][j]      -= f * ga[p][j];
                ga[r][32 + j] -= f * ga[p][32 + j];
                __syncwarp();
            }
            __syncwarp();
        }
        for (int r = 0; r < 32; r++)
            g_Minv[k * 1024 + r * 32 + j] = ga[r][32 + j];
        if (j == 0) g_mcnt[k] = 0;
    }
}

// ---- warp-per-row softmax on CSR support, NO max subtraction ----------------
// scores = (M^-1 z_i) . z_j are all in ~[-1,1] (M ~ 129*I), so exp(p) is
// perfectly conditioned and softmax shift-invariance makes this exact.
// Loop body has NO serial dependency: independent FADD accumulators.
__global__ void __launch_bounds__(256) k_score() {
    __shared__ float sMinv[32 * 33];
    __shared__ float sZr[8][32];
    int k = blockIdx.y;
    int t = threadIdx.x;
    int w = t >> 5, lane = t & 31;
    int g = lane >> 3, sq = lane & 7;
    for (int i = t; i < 1024; i += 256)
        sMinv[(i >> 5) * 33 + (i & 31)] = g_Minv[k * 1024 + i];
    int row = blockIdx.x * 8 + w;
    int beg = g_rowbeg[row];
    int cnt = g_rowcnt[row];
    const float* Zb = g_Z + (size_t)k * NN * SS;
    float4 z4 = *(const float4*)&Zb[(size_t)row * SS + sq * 4];
    if (g == 0) {
        sZr[w][sq * 4 + 0] = z4.x; sZr[w][sq * 4 + 1] = z4.y;
        sZr[w][sq * 4 + 2] = z4.z; sZr[w][sq * 4 + 3] = z4.w;
    }
    __syncthreads();
    // y = M^-1 z (each lane: its 4 s-components)
    float y4[4];
    #pragma unroll
    for (int cc = 0; cc < 4; cc++) {
        int s = sq * 4 + cc;
        float a = 0.f;
        #pragma unroll
        for (int tt = 0; tt < 32; tt++)
            a += sMinv[s * 33 + tt] * sZr[w][tt];
        y4[cc] = a;
    }

    float l = 0.f;
    float4 vac = make_float4(0.f, 0.f, 0.f, 0.f);
    for (int base = 0; base < cnt; base += 4) {
        int idx = base + g;
        bool valid = idx < cnt;
        int ii = valid ? idx : cnt - 1;
        int col = (int)__ldg(&g_cols[beg + ii]);
        float4 f4 = *(const float4*)&Zb[(size_t)col * SS + sq * 4];
        float p = y4[0] * f4.x + y4[1] * f4.y + y4[2] * f4.z + y4[3] * f4.w;
        p += __shfl_xor_sync(FULLM, p, 1);
        p += __shfl_xor_sync(FULLM, p, 2);
        p += __shfl_xor_sync(FULLM, p, 4);
        float e = valid ? __expf(p) : 0.f;
        l += e;
        vac.x += e * f4.x;
        vac.y += e * f4.y;
        vac.z += e * f4.z;
        vac.w += e * f4.w;
    }
    // merge the 4 neighbor-groups (lane bits 3,4): plain sums
    #pragma unroll
    for (int off = 8; off < 32; off <<= 1) {
        l     += __shfl_xor_sync(FULLM, l,     off);
        vac.x += __shfl_xor_sync(FULLM, vac.x, off);
        vac.y += __shfl_xor_sync(FULLM, vac.y, off);
        vac.z += __shfl_xor_sync(FULLM, vac.z, off);
        vac.w += __shfl_xor_sync(FULLM, vac.w, off);
    }
    // r = vac / l; V = M^-1 r
    float inv = 1.0f / l;
    if (g == 0) {
        sZr[w][sq * 4 + 0] = vac.x * inv; sZr[w][sq * 4 + 1] = vac.y * inv;
        sZr[w][sq * 4 + 2] = vac.z * inv; sZr[w][sq * 4 + 3] = vac.w * inv;
    }
    __syncwarp();
    if (g == 0) {
        float o4[4];
        #pragma unroll
        for (int cc = 0; cc < 4; cc++) {
            int s = sq * 4 + cc;
            float a = 0.f;
            #pragma unroll
            for (int tt = 0; tt < 32; tt++)
                a += sMinv[s * 33 + tt] * sZr[w][tt];
            o4[cc] = a;
        }
        float4 o = make_float4(o4[0], o4[1], o4[2], o4[3]);
        *(float4*)&g_V[((size_t)k * NN + row) * SS + sq * 4] = o;
    }
}

// ---- warp-per-row: W_k = w_k * (V_k - lam*(cnt*V_row - sum_nbr V_col)) ------
__global__ void __launch_bounds__(256) k_lapV(const float* __restrict__ lamp) {
    int k = blockIdx.y;
    int w = threadIdx.x >> 5, lane = threadIdx.x & 31;
    int g = lane >> 3, sq = lane & 7;
    int row = blockIdx.x * 8 + w;
    float lam = lamp[0];
    int beg = g_rowbeg[row];
    int cnt = g_rowcnt[row];
    const float* Vb = g_V + (size_t)k * NN * SS;
    float4 s4 = make_float4(0.f, 0.f, 0.f, 0.f);
    for (int base = 0; base < cnt; base += 4) {
        int idx = base + g;
        bool valid = idx < cnt;
        int ii = valid ? idx : cnt - 1;
        int col = (int)__ldg(&g_cols[beg + ii]);
        float sgn = valid ? 1.f : 0.f;
        float4 f4 = *(const float4*)&Vb[(size_t)col * SS + sq * 4];
        s4.x += sgn * f4.x; s4.y += sgn * f4.y; s4.z += sgn * f4.z; s4.w += sgn * f4.w;
    }
    #pragma unroll
    for (int off = 8; off < 32; off <<= 1) {
        s4.x += __shfl_xor_sync(FULLM, s4.x, off);
        s4.y += __shfl_xor_sync(FULLM, s4.y, off);
        s4.z += __shfl_xor_sync(FULLM, s4.z, off);
        s4.w += __shfl_xor_sync(FULLM, s4.w, off);
    }
    if (g == 0) {
        float wk = g_w[k];
        float fc = (float)cnt;
        float4 v4 = *(const float4*)&Vb[(size_t)row * SS + sq * 4];
        float4 o = make_float4(wk * (v4.x - lam * (fc * v4.x - s4.x)),
                               wk * (v4.y - lam * (fc * v4.y - s4.y)),
                               wk * (v4.z - lam * (fc * v4.z - s4.z)),
                               wk * (v4.w - lam * (fc * v4.w - s4.w)));
        *(float4*)&g_W[((size_t)k * NN + row) * SS + sq * 4] = o;
    }
}

// ----- H_out = softthresh(hops0 + 0.5 * sum_k W_k @ U_k^T, thr)  (N x D) -----
__global__ void __launch_bounds__(256) k_vu(const float* __restrict__ U,
                                            const float* __restrict__ hops,
                                            const float* __restrict__ thr,
                                            float* __restrict__ out) {
    __shared__ __align__(16) float sW[32 * 32];
    int d = threadIdx.x, n0 = blockIdx.x * 32;
    float acc[32];
    #pragma unroll
    for (int i = 0; i < 32; i++) acc[i] = 0.f;
    for (int k = 0; k < KK; k++) {
        float u[32];
        const float4* up = (const float4*)(U + (size_t)k * DD * SS + (size_t)d * SS);
        #pragma unroll
        for (int i = 0; i < 8; i++) {
            float4 t = __ldg(&up[i]);
            u[4*i]   = t.x; u[4*i+1] = t.y;
            u[4*i+2] = t.z; u[4*i+3] = t.w;
        }
        __syncthreads();
        for (int i = threadIdx.x; i < 1024; i += 256)
            sW[i] = g_W[(size_t)k * NN * SS + (size_t)n0 * SS + i];
        __syncthreads();
        #pragma unroll 4
        for (int n = 0; n < 32; n++) {
            const float4* vp = (const float4*)&sW[n * 32];
            float a = 0.f;
            #pragma unroll
            for (int s4 = 0; s4 < 8; s4++) {
                float4 v = vp[s4];
                a += u[4*s4]*v.x + u[4*s4+1]*v.y + u[4*s4+2]*v.z + u[4*s4+3]*v.w;
            }
            acc[n] += a;
        }
    }
    float t = thr[d];
    for (int n = 0; n < 32; n++) {
        float hh = hops[(size_t)(n0 + n) * DD + d] + 0.5f * acc[n];
        float o = fmaxf(fabsf(hh) - t, 0.f);
        o = (hh < 0.f) ? -o : o;
        out[(size_t)(n0 + n) * DD + d] = o;
    }
}

// ---- lap_smooth = sum((cnt-1)|h_i|^2) - 2 sum_{i<j in N} h_i.h_j ------------
__global__ void k_lap2(float* out) {
    __shared__ int   sc[256];
    __shared__ float sred[256];
    const float* H = out;
    int row = blockIdx.x, d = threadIdx.x;
    int beg = g_rowbeg[row];
    int cnt = g_rowcnt[row];
    int dpos = g_diagpos[row];
    float hi = H[(size_t)row * DD + d];
    float y = 0.f;
    for (int c0 = dpos + 1; c0 < cnt; c0 += 256) {
        int mm = min(256, cnt - c0);
        __syncthreads();
        if (d < mm) sc[d] = (int)g_cols[beg + c0 + d];
        __syncthreads();
        int e = 0;
        for (; e + 4 <= mm; e += 4) {
            float h0 = H[(size_t)sc[e]     * DD + d];
            float h1 = H[(size_t)sc[e + 1] * DD + d];
            float h2 = H[(size_t)sc[e + 2] * DD + d];
            float h3 = H[(size_t)sc[e + 3] * DD + d];
            y += h0 + h1 + h2 + h3;
        }
        for (; e < mm; e++)
            y += H[(size_t)sc[e] * DD + d];
    }
    sred[d] = hi * ((float)(cnt - 1) * hi - 2.f * y);
    __syncthreads();
    for (int o = 128; o > 0; o >>= 1) {
        if (d < o) sred[d] += sred[d + o];
        __syncthreads();
    }
    if (d == 0) {
        atomicAdd(&out[NDOUT + 1], sred[0]);
        if (row == 0) g_nnz = 0;
    }
}

// -----------------------------------------------------------------------------
extern "C" void kernel_launch(void* const* d_in, const int* in_sizes, int n_in,
                              void* d_out, int out_size) {
    const float* hops = (const float*)d_in[0];  // (K,N,D)
    const float* A    = (const float*)d_in[1];  // (N,N)
    const float* U    = (const float*)d_in[3];  // (K,D,S)
    const float* hw   = (const float*)d_in[4];  // (K,)
    const float* thr  = (const float*)d_in[5];  // (D,)
    const float* lam  = (const float*)d_in[6];  // scalar
    float* out = (float*)d_out;

    k_build<<<NN + 10, 256>>>(A, U, hw, out, out_size);

    dim3 gz(NN / 64, KK);
    k_Z<<<gz, 256>>>(hops, U);
    dim3 gm(MCH, KK);
    k_Mpart<<<gm, 256>>>();
    dim3 gmz(NN / 8, KK);
    k_score<<<gmz, 256>>>();
    k_lapV<<<gmz, 256>>>(lam);
    k_vu<<<NN / 32, 256>>>(U, hops, thr, out);
    k_lap2<<<NN, 256>>>(out);
}